// round 12
// baseline (speedup 1.0000x reference)
#include <cuda_runtime.h>
#include <cstdint>

#define FULLMASK 0xffffffffu
constexpr int Bn = 256;
constexpr int Cn = 40;
constexpr int MAXSW_BIG   = 10;
constexpr int MAXSW_SMALL = 14;
constexpr float TOL_SKIP   = 1e-9f;   // per-step rotation-skip threshold
constexpr float TOLP_BIG   = 1e-6f;   // predictive sweep-termination tolerance
constexpr float TOLP_SMALL = 1e-8f;
constexpr float EPS_BN  = 1e-5f;
constexpr float EIG_EPS = 1e-6f;
constexpr int WPB = 4;   // 128-thread blocks
// per-warp smem: A panel (36*32 floats, float4 rows) + B panel (32*32)
constexpr int SH_PER_WARP = 36*32 + 32*32;   // 2176 floats
constexpr int SMEM_BYTES  = WPB * SH_PER_WARP * 4;   // 34816 B

// ---------------- device scratch ----------------
__device__ __align__(16) float g_BM [Cn*1024];
__device__ __align__(16) float g_S  [Cn*1024];   // BM^{-1/2}
__device__ __align__(16) float g_Q  [Cn*1024];   // BM^{1/2}
__device__ __align__(16) float g_BM2[Cn*1024];   // updated batch mean scratch
__device__ __align__(16) float g_AIS[Cn*1024];   // BM2^{-1/2}
__device__ __align__(16) float g_MSQ[Cn*1024];   // BM2^{(1-t)/2}
__device__ __align__(16) float g_GT [Cn*1024];
__device__ float g_SCALE[Cn];
__device__ float g_SL2[Bn*Cn];
__device__ __align__(16) float g_XT[(size_t)Bn*Cn*1024];   // 41.9 MB
__device__ __align__(16) float g_V [(size_t)Bn*Cn*1024];   // 41.9 MB eigenvector cache
__device__ float4 g_P[8*Cn*256];

// ---------------- helpers ----------------
__device__ __forceinline__ float warp_sum(float v){
#pragma unroll
  for(int o=16;o>0;o>>=1) v += __shfl_xor_sync(FULLMASK, v, o);
  return v;
}

typedef unsigned long long u64;

__device__ __forceinline__ u64 pk2(float lo, float hi){
  u64 r; asm("mov.b64 %0, {%1,%2};" : "=l"(r) : "f"(lo), "f"(hi)); return r;
}
__device__ __forceinline__ void upk2(float& lo, float& hi, u64 v){
  asm("mov.b64 {%0,%1}, %2;" : "=f"(lo), "=f"(hi) : "l"(v));
}
__device__ __forceinline__ u64 ffma2(u64 a, u64 b, u64 c){
  u64 d; asm("fma.rn.f32x2 %0, %1, %2, %3;" : "=l"(d) : "l"(a), "l"(b), "l"(c));
  return d;
}
__device__ __forceinline__ u64 fmul2(u64 a, u64 b){
  u64 d; asm("mul.rn.f32x2 %0, %1, %2;" : "=l"(d) : "l"(a), "l"(b));
  return d;
}
__device__ __forceinline__ u64 fadd2(u64 a, u64 b){
  u64 d; asm("add.rn.f32x2 %0, %1, %2;" : "=l"(d) : "l"(a), "l"(b));
  return d;
}

__device__ __forceinline__ void packv(u64* A, const float* a){
#pragma unroll
  for(int i=0;i<16;i++) A[i] = pk2(a[2*i], a[2*i+1]);
}
__device__ __forceinline__ void unpackv(float* a, const u64* A){
#pragma unroll
  for(int i=0;i<16;i++) upk2(a[2*i], a[2*i+1], A[i]);
}

// shared mm core: consumes staged shA (col-major, stride 36) and shB (row-major)
__device__ __forceinline__ void mm_core(float* out, float* shA, float* shB, int lane){
  u64 acc[16];
#pragma unroll
  for(int p=0;p<16;p++) acc[p] = 0ull;
#pragma unroll 2
  for(int k=0;k<32;k++){
    float bk = shB[k*32+lane];
    u64 bb = pk2(bk, bk);
    const float4* col = reinterpret_cast<const float4*>(shA + k*36);
#pragma unroll
    for(int u=0;u<8;u++){
      float4 f = col[u];
      acc[2*u]   = ffma2(pk2(f.x, f.y), bb, acc[2*u]);
      acc[2*u+1] = ffma2(pk2(f.z, f.w), bb, acc[2*u+1]);
    }
  }
#pragma unroll
  for(int p=0;p<16;p++) upk2(out[2*p], out[2*p+1], acc[p]);
  __syncwarp();
}

// out = A*B, column-per-lane (lane j holds column j). out may alias a or b.
__device__ __forceinline__ void mm32(float* out, const float* a, const float* b,
                                     float* sh, int lane){
  float* shA = sh;
  float* shB = sh + 36*32;
  __syncwarp();
  {
    float4* dst = reinterpret_cast<float4*>(shA + lane*36);
#pragma unroll
    for(int u=0;u<8;u++) dst[u] = make_float4(a[4*u],a[4*u+1],a[4*u+2],a[4*u+3]);
  }
#pragma unroll
  for(int i=0;i<32;i++) shB[i*32+lane] = b[i];
  __syncwarp();
  mm_core(out, shA, shB, lane);
}

// out = A * B with B read straight from global (row-major [i*32+j], 16B aligned)
__device__ __forceinline__ void mm32_bg(float* out, const float* a,
                                        const float* __restrict__ gB,
                                        float* sh, int lane){
  float* shA = sh;
  float* shB = sh + 36*32;
  __syncwarp();
  {
    float4* dst = reinterpret_cast<float4*>(shA + lane*36);
#pragma unroll
    for(int u=0;u<8;u++) dst[u] = make_float4(a[4*u],a[4*u+1],a[4*u+2],a[4*u+3]);
  }
  {
    const float4* g4 = reinterpret_cast<const float4*>(gB);
    float4* s4 = reinterpret_cast<float4*>(shB);
#pragma unroll
    for(int u=0;u<8;u++) s4[u*32+lane] = g4[u*32+lane];
  }
  __syncwarp();
  mm_core(out, shA, shB, lane);
}

// dst = rows of src (columns of src^T)
__device__ __forceinline__ void transp32(float* dst, const float* src,
                                         float* sh, int lane){
  __syncwarp();
#pragma unroll
  for(int i=0;i<32;i++) sh[i*33+lane] = src[i];
  __syncwarp();
#pragma unroll
  for(int k=0;k<32;k++) dst[k] = sh[lane*33+k];
  __syncwarp();
}

// ---- Jacobi building blocks (f32x2-packed columns) ----

__device__ __forceinline__ float colnorm2(const u64* A){
  u64 na=0ull, nb=0ull;
#pragma unroll
  for(int i=0;i<16;i+=2){ na = ffma2(A[i],A[i],na); nb = ffma2(A[i+1],A[i+1],nb); }
  float xl,xh,yl,yh; upk2(xl,xh,na); upk2(yl,yh,nb);
  return (xl+xh)+(yl+yh);
}

// one pair-step (distance r) of one-sided Jacobi.
// - rotation update SKIPPED when the whole warp is below TOL_SKIP
// - conv accumulates the looser predictive-termination predicate (tolp)
__device__ __forceinline__ void jstep(u64* A, float& alpha, bool& conv,
                                      int r, int lane, float tolp){
  u64 Bv[16];
  u64 q0=0ull, q1=0ull, q2=0ull, q3=0ull;
#pragma unroll
  for(int i=0;i<16;i+=4){
    Bv[i]   = __shfl_xor_sync(FULLMASK, A[i],   r);
    Bv[i+1] = __shfl_xor_sync(FULLMASK, A[i+1], r);
    Bv[i+2] = __shfl_xor_sync(FULLMASK, A[i+2], r);
    Bv[i+3] = __shfl_xor_sync(FULLMASK, A[i+3], r);
    q0 = ffma2(A[i],  Bv[i],  q0);
    q1 = ffma2(A[i+1],Bv[i+1],q1);
    q2 = ffma2(A[i+2],Bv[i+2],q2);
    q3 = ffma2(A[i+3],Bv[i+3],q3);
  }
  u64 qc = fadd2(fadd2(q0,q1), fadd2(q2,q3));
  float xl,xh; upk2(xl,xh,qc);
  float gamma = xl+xh;
  float beta  = __shfl_xor_sync(FULLMASK, alpha, r);
  bool  isp   = lane < (lane ^ r);
  float app   = isp ? alpha : beta;
  float aqq   = isp ? beta  : alpha;
  float gg    = gamma*gamma;
  float dd    = app*aqq;
  bool skipc  = gg <= TOL_SKIP*dd;
  conv = conv && (gg <= tolp*dd);
  // speculative rotation scalars (half-angle form; overlap the vote)
  float d    = aqq - app;
  float g2   = gamma + gamma;
  float rh   = rsqrtf(fmaf(d,d, g2*g2));   // 1/h
  float cos2 = fabsf(d)*rh;                 // cos(2θ), |θ|<=π/4
  float c2   = fmaf(0.5f, cos2, 0.5f);      // cos²θ
  float rc   = rsqrtf(c2);                  // 1/c
  float c0   = c2*rc;                       // c
  float sgn  = copysignf(1.f, d);
  float s0   = gamma*sgn*rh*rc;             // sinθ
  float t0   = s0*rc;                       // tanθ
  bool  rot  = gg > 1e-28f*dd;
  float c = rot ? c0 : 1.f;
  float s = rot ? s0 : 0.f;
  float t = rot ? t0 : 0.f;
  if(!__all_sync(FULLMASK, skipc)){
    float se = isp ? -s : s;
    float te = isp ? -t : t;
    u64 C2 = pk2(c,c), S2 = pk2(se,se);
#pragma unroll
    for(int i=0;i<16;i++) A[i] = ffma2(S2, Bv[i], fmul2(C2, A[i]));
    alpha = fmaf(te, gamma, alpha);
  }
}

__device__ __forceinline__ float jfinish(u64* A){
  float nn  = colnorm2(A);
  float inv = rsqrtf(nn);
  u64 I2 = pk2(inv,inv);
#pragma unroll
  for(int i=0;i<16;i++) A[i] = fmul2(I2, A[i]);
  return nn*inv;   // sqrt(nn) = eigenvalue (SPD)
}

// One-sided Jacobi: predictive termination + per-step skip-vote.
template<int MAXSWEEP>
__device__ __forceinline__ float jacobi_vf(float* a, int lane, float tolp){
  u64 A[16];
  packv(A, a);
#pragma unroll 1
  for(int sw=0; sw<MAXSWEEP; ++sw){
    float alpha = colnorm2(A);   // exact norm refresh each sweep
    bool conv = true;
#pragma unroll 1
    for(int r=1;r<32;r++) jstep(A, alpha, conv, r, lane, tolp);
    if(__all_sync(FULLMASK, conv)) break;
  }
  float lam = jfinish(A);
  unpackv(a, A);
  return lam;
}

// dual-matrix Jacobi: two independent eigenproblems interleaved for ILP.
// Intended for single-warp-per-SM kernels where occupancy can't hide latency.
template<int MAXSWEEP>
__device__ __forceinline__ void jacobi_dual(u64* A1, u64* A2, int lane, float tolp,
                                            float& lam1, float& lam2){
#pragma unroll 1
  for(int sw=0; sw<MAXSWEEP; ++sw){
    float a1 = colnorm2(A1);
    float a2 = colnorm2(A2);
    bool c1 = true, c2 = true;
#pragma unroll 1
    for(int r=1;r<32;r++){
      jstep(A1, a1, c1, r, lane, tolp);
      jstep(A2, a2, c2, r, lane, tolp);
    }
    if(__all_sync(FULLMASK, c1 && c2)) break;
  }
  lam1 = jfinish(A1);
  lam2 = jfinish(A2);
}

// ================= kernels =================

__global__ void k_mean1(const float4* __restrict__ X4){
  int idx = blockIdx.x*blockDim.x + threadIdx.x;
  int s   = blockIdx.y;
  float4 acc = make_float4(0.f,0.f,0.f,0.f);
  const float4* p = X4 + (size_t)(s*32)*(Cn*256) + idx;
#pragma unroll 4
  for(int b=0;b<32;b++){
    float4 v = p[(size_t)b*(Cn*256)];
    acc.x += v.x; acc.y += v.y; acc.z += v.z; acc.w += v.w;
  }
  g_P[s*(Cn*256)+idx] = acc;
}

__global__ void k_mean2(){
  int idx = blockIdx.x*blockDim.x + threadIdx.x;
  float4 acc = make_float4(0.f,0.f,0.f,0.f);
#pragma unroll
  for(int s=0;s<8;s++){
    float4 v = g_P[s*(Cn*256)+idx];
    acc.x += v.x; acc.y += v.y; acc.z += v.z; acc.w += v.w;
  }
  const float sc = 1.f/Bn;
  acc.x*=sc; acc.y*=sc; acc.z*=sc; acc.w*=sc;
  reinterpret_cast<float4*>(g_BM)[idx] = acc;
}

// eigh(BM) -> Q = BM^{1/2}, S = BM^{-1/2}; 2 channels per warp (dual ILP)
__global__ __launch_bounds__(32) void k_phaseB(){
  __shared__ __align__(16) float sh[SH_PER_WARP];
  int lane = threadIdx.x;
  int c0 = blockIdx.x, c1 = blockIdx.x + Cn/2;
  float v1[32], v2[32];
#pragma unroll
  for(int i=0;i<32;i++) v1[i] = g_BM[c0*1024 + i*32 + lane];
#pragma unroll
  for(int i=0;i<32;i++) v2[i] = g_BM[c1*1024 + i*32 + lane];
  u64 A1[16], A2[16];
  packv(A1, v1); packv(A2, v2);
  float lam1, lam2;
  jacobi_dual<MAXSW_SMALL>(A1, A2, lane, TOLP_SMALL, lam1, lam2);
  unpackv(v1, A1); unpackv(v2, A2);
  // epilogue c0
  {
    float vr[32], w[32], o[32];
    float sq = sqrtf(fmaxf(lam1, EIG_EPS));
    transp32(vr, v1, sh, lane);
#pragma unroll
    for(int i=0;i<32;i++) w[i] = v1[i]*sq;
    mm32(o, w, vr, sh, lane);
#pragma unroll
    for(int i=0;i<32;i++) g_Q[c0*1024+i*32+lane] = o[i];
    float isq = 1.f/sq;
#pragma unroll
    for(int i=0;i<32;i++) w[i] = v1[i]*isq;
    mm32(o, w, vr, sh, lane);
#pragma unroll
    for(int i=0;i<32;i++) g_S[c0*1024+i*32+lane] = o[i];
  }
  // epilogue c1
  {
    float vr[32], w[32], o[32];
    float sq = sqrtf(fmaxf(lam2, EIG_EPS));
    transp32(vr, v2, sh, lane);
#pragma unroll
    for(int i=0;i<32;i++) w[i] = v2[i]*sq;
    mm32(o, w, vr, sh, lane);
#pragma unroll
    for(int i=0;i<32;i++) g_Q[c1*1024+i*32+lane] = o[i];
    float isq = 1.f/sq;
#pragma unroll
    for(int i=0;i<32;i++) w[i] = v2[i]*isq;
    mm32(o, w, vr, sh, lane);
#pragma unroll
    for(int i=0;i<32;i++) g_S[c1*1024+i*32+lane] = o[i];
  }
}

// per (b,c): Y = S X S; eigh; cache V; XT = V log(l) V^T; store XT + sum(log^2 l)
__global__ __launch_bounds__(WPB*32,6) void k_phaseC(const float* __restrict__ X){
  extern __shared__ __align__(16) float dsh[];
  int warp = threadIdx.x >> 5, lane = threadIdx.x & 31;
  float* sh = dsh + warp*SH_PER_WARP;
  int task = blockIdx.x*WPB + warp;
  int c = task % Cn;
  float x[32], s[32];
  const float* xp = X + (size_t)task*1024;
#pragma unroll
  for(int i=0;i<32;i++) s[i] = g_S[c*1024+i*32+lane];
  mm32_bg(x, s, xp, sh, lane);              // S*X
  mm32(x, x, s, sh, lane);                  // (S X) S
  float lam = jacobi_vf<MAXSW_BIG>(x, lane, TOLP_BIG); // x -> V
  float lg  = logf(fmaxf(lam, EIG_EPS));
  float sl2 = warp_sum(lg*lg);
  if(lane==0) g_SL2[task] = sl2;
  float* vp = g_V + (size_t)task*1024;
#pragma unroll
  for(int i=0;i<32;i++) vp[i*32+lane] = x[i];   // cache V for phase F
  transp32(s, x, sh, lane);                 // rows of V
#pragma unroll
  for(int i=0;i<32;i++) x[i] *= lg;         // V diag(log l)
  mm32(x, x, s, sh, lane);                  // XT
  float* op = g_XT + (size_t)task*1024;
#pragma unroll
  for(int i=0;i<32;i++) op[i*32+lane] = x[i];
}

__global__ void k_reduce1(){
  int idx = blockIdx.x*blockDim.x + threadIdx.x;
  int s   = blockIdx.y;
  float4 acc = make_float4(0.f,0.f,0.f,0.f);
  const float4* p = reinterpret_cast<const float4*>(g_XT) + (size_t)(s*32)*(Cn*256) + idx;
#pragma unroll 4
  for(int b=0;b<32;b++){
    float4 v = p[(size_t)b*(Cn*256)];
    acc.x += v.x; acc.y += v.y; acc.z += v.z; acc.w += v.w;
  }
  g_P[s*(Cn*256)+idx] = acc;
}

__global__ void k_reduce2(){
  int idx = blockIdx.x*blockDim.x + threadIdx.x;
  float4 acc = make_float4(0.f,0.f,0.f,0.f);
#pragma unroll
  for(int s=0;s<8;s++){
    float4 v = g_P[s*(Cn*256)+idx];
    acc.x += v.x; acc.y += v.y; acc.z += v.z; acc.w += v.w;
  }
  const float sc = 1.f/Bn;
  acc.x*=sc; acc.y*=sc; acc.z*=sc; acc.w*=sc;
  reinterpret_cast<float4*>(g_GT)[idx] = acc;
}

// ETA==1 collapse: rm = BM2 = Q expm(GT) Q, GT_rm = GT.
// AIS = BM2^{-1/2}, MSQ = BM2^{(1-t)/2}, SCALE = std/sqrt(var+eps),
// var = mean||XT||^2 - ||GT||^2.  2 channels per warp (dual ILP).
__global__ __launch_bounds__(32) void k_chan(const float* __restrict__ std_,
                                             const float* __restrict__ pt){
  __shared__ __align__(16) float sh[SH_PER_WARP];
  int lane = threadIdx.x;
  int c0 = blockIdx.x, c1 = blockIdx.x + Cn/2;
  float v1[32], v2[32];
  float f2a = 0.f, f2b = 0.f;
#pragma unroll
  for(int i=0;i<32;i++){ v1[i] = g_GT[c0*1024+i*32+lane]; f2a = fmaf(v1[i],v1[i],f2a); }
#pragma unroll
  for(int i=0;i<32;i++){ v2[i] = g_GT[c1*1024+i*32+lane]; f2b = fmaf(v2[i],v2[i],f2b); }
  f2a = warp_sum(f2a); f2b = warp_sum(f2b);
  float sh1 = sqrtf(f2a) + 1.f, sh2 = sqrtf(f2b) + 1.f;
#pragma unroll
  for(int i=0;i<32;i++){
    v1[i] += (i==lane) ? sh1 : 0.f;
    v2[i] += (i==lane) ? sh2 : 0.f;
  }
  u64 A1[16], A2[16];
  packv(A1, v1); packv(A2, v2);
  float lam1, lam2;
  jacobi_dual<MAXSW_SMALL>(A1, A2, lane, TOLP_SMALL, lam1, lam2);
  unpackv(v1, A1); unpackv(v2, A2);
  float e1 = expf(lam1 - sh1), e2 = expf(lam2 - sh2);
  // BM2 per channel -> global scratch (caps register pressure)
  {
    float vr[32], w[32], t[32];
    transp32(vr, v1, sh, lane);
#pragma unroll
    for(int i=0;i<32;i++) w[i] = v1[i]*e1;
    mm32(t, w, vr, sh, lane);              // expm(GT)
#pragma unroll
    for(int i=0;i<32;i++) w[i] = g_Q[c0*1024+i*32+lane];
    mm32(t, w, t, sh, lane);               // Q expm
    mm32(t, t, w, sh, lane);               // Q expm Q
#pragma unroll
    for(int i=0;i<32;i++) g_BM2[c0*1024+i*32+lane] = t[i];
  }
  {
    float vr[32], w[32], t[32];
    transp32(vr, v2, sh, lane);
#pragma unroll
    for(int i=0;i<32;i++) w[i] = v2[i]*e2;
    mm32(t, w, vr, sh, lane);
#pragma unroll
    for(int i=0;i<32;i++) w[i] = g_Q[c1*1024+i*32+lane];
    mm32(t, w, t, sh, lane);
    mm32(t, t, w, sh, lane);
#pragma unroll
    for(int i=0;i<32;i++) g_BM2[c1*1024+i*32+lane] = t[i];
  }
  // dual eigh of BM2 pair
#pragma unroll
  for(int i=0;i<32;i++) v1[i] = g_BM2[c0*1024+i*32+lane];
#pragma unroll
  for(int i=0;i<32;i++) v2[i] = g_BM2[c1*1024+i*32+lane];
  packv(A1, v1); packv(A2, v2);
  jacobi_dual<MAXSW_SMALL>(A1, A2, lane, TOLP_SMALL, lam1, lam2);
  unpackv(v1, A1); unpackv(v2, A2);
  float mu1 = fmaxf(lam1, EIG_EPS), mu2 = fmaxf(lam2, EIG_EPS);
  float tp = pt[0];
  // AIS / MSQ per channel
  {
    float vr[32], w[32], o[32];
    transp32(vr, v1, sh, lane);
    float ris = rsqrtf(mu1);
#pragma unroll
    for(int i=0;i<32;i++) w[i] = v1[i]*ris;
    mm32(o, w, vr, sh, lane);
#pragma unroll
    for(int i=0;i<32;i++) g_AIS[c0*1024+i*32+lane] = o[i];
    float me = expf(0.5f*(1.f - tp)*logf(mu1));
#pragma unroll
    for(int i=0;i<32;i++) w[i] = v1[i]*me;
    mm32(o, w, vr, sh, lane);
#pragma unroll
    for(int i=0;i<32;i++) g_MSQ[c0*1024+i*32+lane] = o[i];
  }
  {
    float vr[32], w[32], o[32];
    transp32(vr, v2, sh, lane);
    float ris = rsqrtf(mu2);
#pragma unroll
    for(int i=0;i<32;i++) w[i] = v2[i]*ris;
    mm32(o, w, vr, sh, lane);
#pragma unroll
    for(int i=0;i<32;i++) g_AIS[c1*1024+i*32+lane] = o[i];
    float me = expf(0.5f*(1.f - tp)*logf(mu2));
#pragma unroll
    for(int i=0;i<32;i++) w[i] = v2[i]*me;
    mm32(o, w, vr, sh, lane);
#pragma unroll
    for(int i=0;i<32;i++) g_MSQ[c1*1024+i*32+lane] = o[i];
  }
  // SCALE per channel
  float pa = 0.f, pb = 0.f;
  for(int b=lane;b<Bn;b+=32){ pa += g_SL2[b*Cn + c0]; pb += g_SL2[b*Cn + c1]; }
  float ma = warp_sum(pa) * (1.f/Bn);
  float mb = warp_sum(pb) * (1.f/Bn);
  if(lane==0){
    g_SCALE[c0] = std_[c0] * rsqrtf((ma - f2a) + EPS_BN);
    g_SCALE[c1] = std_[c1] * rsqrtf((mb - f2b) + EPS_BN);
  }
}

// per (b,c): warm-started eigh of Z = AIS X AIS using cached V from phase C:
// W = (AIS V)^T X (AIS V) is nearly diagonal -> few sweeps.
// Xn = G G^T, G = MSQ (V Vw) diag(l^{s/2})
__global__ __launch_bounds__(WPB*32,6) void k_phaseF(const float* __restrict__ X,
                                                     float* __restrict__ out){
  extern __shared__ __align__(16) float dsh[];
  int warp = threadIdx.x >> 5, lane = threadIdx.x & 31;
  float* sh = dsh + warp*SH_PER_WARP;
  int task = blockIdx.x*WPB + warp;
  int c = task % Cn;
  float v[32], p[32], t[32], w[32];
  const float* xp = X + (size_t)task*1024;
  const float* vp = g_V + (size_t)task*1024;
#pragma unroll
  for(int i=0;i<32;i++) v[i] = vp[i*32+lane];       // V (cols)
#pragma unroll
  for(int i=0;i<32;i++) t[i] = g_AIS[c*1024+i*32+lane];
  mm32(p, t, v, sh, lane);                 // P = AIS * V
  transp32(t, p, sh, lane);                // Pt
  mm32_bg(t, t, xp, sh, lane);             // Pt * X
  mm32(w, t, p, sh, lane);                 // W = Pt X P  (near diagonal)
  float lam = jacobi_vf<MAXSW_BIG>(w, lane, TOLP_BIG);  // w -> Vw
  float sc  = g_SCALE[c];
  float sd  = expf(0.5f*sc * logf(fmaxf(lam, EIG_EPS)));  // lambda^{s/2}
#pragma unroll
  for(int i=0;i<32;i++) t[i] = g_MSQ[c*1024+i*32+lane];
  mm32(v, t, v, sh, lane);                 // H = MSQ * V
  mm32(w, v, w, sh, lane);                 // G0 = H * Vw
#pragma unroll
  for(int i=0;i<32;i++) w[i] *= sd;        // G
  transp32(v, w, sh, lane);                // rows of G
  mm32(p, w, v, sh, lane);                 // G G^T
  float* op = out + (size_t)task*1024;
#pragma unroll
  for(int i=0;i<32;i++) op[i*32+lane] = p[i];
}

// ================= launcher =================
extern "C" void kernel_launch(void* const* d_in, const int* in_sizes, int n_in,
                              void* d_out, int out_size){
  const float* X     = (const float*)d_in[0];
  const float* std_  = (const float*)d_in[1];
  const float* pt    = (const float*)d_in[4];
  float* out = (float*)d_out;

  cudaFuncSetAttribute(k_phaseC, cudaFuncAttributeMaxDynamicSharedMemorySize, SMEM_BYTES);
  cudaFuncSetAttribute(k_phaseF, cudaFuncAttributeMaxDynamicSharedMemorySize, SMEM_BYTES);

  const int nblk = (Bn*Cn)/WPB;   // 2560 blocks of 4 warps

  k_mean1  <<<dim3(Cn, 8), 256>>>((const float4*)X);
  k_mean2  <<<Cn, 256>>>();
  k_phaseB <<<Cn/2, 32>>>();
  k_phaseC <<<nblk, WPB*32, SMEM_BYTES>>>(X);
  k_reduce1<<<dim3(Cn, 8), 256>>>();
  k_reduce2<<<Cn, 256>>>();
  k_chan   <<<Cn/2, 32>>>(std_, pt);
  k_phaseF <<<nblk, WPB*32, SMEM_BYTES>>>(X, out);
}

// round 13
// speedup vs baseline: 1.0590x; 1.0590x over previous
#include <cuda_runtime.h>
#include <cstdint>

#define FULLMASK 0xffffffffu
constexpr int Bn = 256;
constexpr int Cn = 40;
constexpr int MAXSW_BIG   = 10;
constexpr int MAXSW_SMALL = 14;
constexpr float TOL_SKIP   = 1e-9f;   // per-step rotation-skip threshold
constexpr float TOLP_BIG   = 1e-6f;   // predictive sweep-termination tolerance
constexpr float TOLP_SMALL = 1e-8f;
constexpr float EPS_BN  = 1e-5f;
constexpr float EIG_EPS = 1e-6f;
constexpr int WPB = 4;   // 128-thread blocks
// per-warp smem: A panel (36*32 floats, float4 rows) + B panel (32*32)
constexpr int SH_PER_WARP = 36*32 + 32*32;   // 2176 floats
constexpr int SMEM_BYTES  = WPB * SH_PER_WARP * 4;   // 34816 B

// ---------------- device scratch ----------------
__device__ __align__(16) float g_BM [Cn*1024];
__device__ __align__(16) float g_S  [Cn*1024];   // BM^{-1/2}
__device__ __align__(16) float g_Q  [Cn*1024];   // BM^{1/2}
__device__ __align__(16) float g_AIS[Cn*1024];   // BM2^{-1/2}
__device__ __align__(16) float g_MSQ[Cn*1024];   // BM2^{(1-t)/2}
__device__ __align__(16) float g_GT [Cn*1024];
__device__ float g_SCALE[Cn];
__device__ float g_SL2[Bn*Cn];
__device__ __align__(16) float g_XT[(size_t)Bn*Cn*1024];   // 41.9 MB
__device__ __align__(16) float g_V [(size_t)Bn*Cn*1024];   // 41.9 MB eigenvector cache
__device__ float4 g_P[8*Cn*256];

// ---------------- helpers ----------------
__device__ __forceinline__ float warp_sum(float v){
#pragma unroll
  for(int o=16;o>0;o>>=1) v += __shfl_xor_sync(FULLMASK, v, o);
  return v;
}

typedef unsigned long long u64;

__device__ __forceinline__ u64 pk2(float lo, float hi){
  u64 r; asm("mov.b64 %0, {%1,%2};" : "=l"(r) : "f"(lo), "f"(hi)); return r;
}
__device__ __forceinline__ void upk2(float& lo, float& hi, u64 v){
  asm("mov.b64 {%0,%1}, %2;" : "=f"(lo), "=f"(hi) : "l"(v));
}
__device__ __forceinline__ u64 ffma2(u64 a, u64 b, u64 c){
  u64 d; asm("fma.rn.f32x2 %0, %1, %2, %3;" : "=l"(d) : "l"(a), "l"(b), "l"(c));
  return d;
}
__device__ __forceinline__ u64 fmul2(u64 a, u64 b){
  u64 d; asm("mul.rn.f32x2 %0, %1, %2;" : "=l"(d) : "l"(a), "l"(b));
  return d;
}
__device__ __forceinline__ u64 fadd2(u64 a, u64 b){
  u64 d; asm("add.rn.f32x2 %0, %1, %2;" : "=l"(d) : "l"(a), "l"(b));
  return d;
}

__device__ __forceinline__ void packv(u64* A, const float* a){
#pragma unroll
  for(int i=0;i<16;i++) A[i] = pk2(a[2*i], a[2*i+1]);
}
__device__ __forceinline__ void unpackv(float* a, const u64* A){
#pragma unroll
  for(int i=0;i<16;i++) upk2(a[2*i], a[2*i+1], A[i]);
}

// shared mm core: consumes staged shA (col-major, stride 36) and shB (row-major)
__device__ __forceinline__ void mm_core(float* out, float* shA, float* shB, int lane){
  u64 acc[16];
#pragma unroll
  for(int p=0;p<16;p++) acc[p] = 0ull;
#pragma unroll 2
  for(int k=0;k<32;k++){
    float bk = shB[k*32+lane];
    u64 bb = pk2(bk, bk);
    const float4* col = reinterpret_cast<const float4*>(shA + k*36);
#pragma unroll
    for(int u=0;u<8;u++){
      float4 f = col[u];
      acc[2*u]   = ffma2(pk2(f.x, f.y), bb, acc[2*u]);
      acc[2*u+1] = ffma2(pk2(f.z, f.w), bb, acc[2*u+1]);
    }
  }
#pragma unroll
  for(int p=0;p<16;p++) upk2(out[2*p], out[2*p+1], acc[p]);
  __syncwarp();
}

// out = A*B, column-per-lane (lane j holds column j). out may alias a or b.
__device__ __forceinline__ void mm32(float* out, const float* a, const float* b,
                                     float* sh, int lane){
  float* shA = sh;
  float* shB = sh + 36*32;
  __syncwarp();
  {
    float4* dst = reinterpret_cast<float4*>(shA + lane*36);
#pragma unroll
    for(int u=0;u<8;u++) dst[u] = make_float4(a[4*u],a[4*u+1],a[4*u+2],a[4*u+3]);
  }
#pragma unroll
  for(int i=0;i<32;i++) shB[i*32+lane] = b[i];
  __syncwarp();
  mm_core(out, shA, shB, lane);
}

// out = A * B with B read straight from global (row-major [i*32+j], 16B aligned)
__device__ __forceinline__ void mm32_bg(float* out, const float* a,
                                        const float* __restrict__ gB,
                                        float* sh, int lane){
  float* shA = sh;
  float* shB = sh + 36*32;
  __syncwarp();
  {
    float4* dst = reinterpret_cast<float4*>(shA + lane*36);
#pragma unroll
    for(int u=0;u<8;u++) dst[u] = make_float4(a[4*u],a[4*u+1],a[4*u+2],a[4*u+3]);
  }
  {
    const float4* g4 = reinterpret_cast<const float4*>(gB);
    float4* s4 = reinterpret_cast<float4*>(shB);
#pragma unroll
    for(int u=0;u<8;u++) s4[u*32+lane] = g4[u*32+lane];
  }
  __syncwarp();
  mm_core(out, shA, shB, lane);
}

// dst = rows of src (columns of src^T)
__device__ __forceinline__ void transp32(float* dst, const float* src,
                                         float* sh, int lane){
  __syncwarp();
#pragma unroll
  for(int i=0;i<32;i++) sh[i*33+lane] = src[i];
  __syncwarp();
#pragma unroll
  for(int k=0;k<32;k++) dst[k] = sh[lane*33+k];
  __syncwarp();
}

// ---- Jacobi building blocks (f32x2-packed columns) ----

__device__ __forceinline__ float colnorm2(const u64* A){
  u64 na=0ull, nb=0ull;
#pragma unroll
  for(int i=0;i<16;i+=2){ na = ffma2(A[i],A[i],na); nb = ffma2(A[i+1],A[i+1],nb); }
  float xl,xh,yl,yh; upk2(xl,xh,na); upk2(yl,yh,nb);
  return (xl+xh)+(yl+yh);
}

// one pair-step (distance r) of one-sided Jacobi.
// - rotation update SKIPPED when the whole warp is below TOL_SKIP
// - conv accumulates the looser predictive-termination predicate (tolp)
__device__ __forceinline__ void jstep(u64* A, float& alpha, bool& conv,
                                      int r, int lane, float tolp){
  u64 Bv[16];
  u64 q0=0ull, q1=0ull, q2=0ull, q3=0ull;
#pragma unroll
  for(int i=0;i<16;i+=4){
    Bv[i]   = __shfl_xor_sync(FULLMASK, A[i],   r);
    Bv[i+1] = __shfl_xor_sync(FULLMASK, A[i+1], r);
    Bv[i+2] = __shfl_xor_sync(FULLMASK, A[i+2], r);
    Bv[i+3] = __shfl_xor_sync(FULLMASK, A[i+3], r);
    q0 = ffma2(A[i],  Bv[i],  q0);
    q1 = ffma2(A[i+1],Bv[i+1],q1);
    q2 = ffma2(A[i+2],Bv[i+2],q2);
    q3 = ffma2(A[i+3],Bv[i+3],q3);
  }
  u64 qc = fadd2(fadd2(q0,q1), fadd2(q2,q3));
  float xl,xh; upk2(xl,xh,qc);
  float gamma = xl+xh;
  float beta  = __shfl_xor_sync(FULLMASK, alpha, r);
  bool  isp   = lane < (lane ^ r);
  float app   = isp ? alpha : beta;
  float aqq   = isp ? beta  : alpha;
  float gg    = gamma*gamma;
  float dd    = app*aqq;
  bool skipc  = gg <= TOL_SKIP*dd;
  conv = conv && (gg <= tolp*dd);
  // speculative rotation scalars (half-angle form; overlap the vote)
  float d    = aqq - app;
  float g2   = gamma + gamma;
  float rh   = rsqrtf(fmaf(d,d, g2*g2));   // 1/h
  float cos2 = fabsf(d)*rh;                 // cos(2θ), |θ|<=π/4
  float c2   = fmaf(0.5f, cos2, 0.5f);      // cos²θ
  float rc   = rsqrtf(c2);                  // 1/c
  float c0   = c2*rc;                       // c
  float sgn  = copysignf(1.f, d);
  float s0   = gamma*sgn*rh*rc;             // sinθ
  float t0   = s0*rc;                       // tanθ
  bool  rot  = gg > 1e-28f*dd;
  float c = rot ? c0 : 1.f;
  float s = rot ? s0 : 0.f;
  float t = rot ? t0 : 0.f;
  if(!__all_sync(FULLMASK, skipc)){
    float se = isp ? -s : s;
    float te = isp ? -t : t;
    u64 C2 = pk2(c,c), S2 = pk2(se,se);
#pragma unroll
    for(int i=0;i<16;i++) A[i] = ffma2(S2, Bv[i], fmul2(C2, A[i]));
    alpha = fmaf(te, gamma, alpha);
  }
}

__device__ __forceinline__ float jfinish(u64* A){
  float nn  = colnorm2(A);
  float inv = rsqrtf(nn);
  u64 I2 = pk2(inv,inv);
#pragma unroll
  for(int i=0;i<16;i++) A[i] = fmul2(I2, A[i]);
  return nn*inv;   // sqrt(nn) = eigenvalue (SPD)
}

// One-sided Jacobi: predictive termination + per-step skip-vote.
template<int MAXSWEEP>
__device__ __forceinline__ float jacobi_vf(float* a, int lane, float tolp){
  u64 A[16];
  packv(A, a);
#pragma unroll 1
  for(int sw=0; sw<MAXSWEEP; ++sw){
    float alpha = colnorm2(A);   // exact norm refresh each sweep
    bool conv = true;
#pragma unroll 1
    for(int r=1;r<32;r++) jstep(A, alpha, conv, r, lane, tolp);
    if(__all_sync(FULLMASK, conv)) break;
  }
  float lam = jfinish(A);
  unpackv(a, A);
  return lam;
}

// ================= kernels =================

__global__ void k_mean1(const float4* __restrict__ X4){
  int idx = blockIdx.x*blockDim.x + threadIdx.x;
  int s   = blockIdx.y;
  float4 acc = make_float4(0.f,0.f,0.f,0.f);
  const float4* p = X4 + (size_t)(s*32)*(Cn*256) + idx;
#pragma unroll 4
  for(int b=0;b<32;b++){
    float4 v = p[(size_t)b*(Cn*256)];
    acc.x += v.x; acc.y += v.y; acc.z += v.z; acc.w += v.w;
  }
  g_P[s*(Cn*256)+idx] = acc;
}

__global__ void k_mean2(){
  int idx = blockIdx.x*blockDim.x + threadIdx.x;
  float4 acc = make_float4(0.f,0.f,0.f,0.f);
#pragma unroll
  for(int s=0;s<8;s++){
    float4 v = g_P[s*(Cn*256)+idx];
    acc.x += v.x; acc.y += v.y; acc.z += v.z; acc.w += v.w;
  }
  const float sc = 1.f/Bn;
  acc.x*=sc; acc.y*=sc; acc.z*=sc; acc.w*=sc;
  reinterpret_cast<float4*>(g_BM)[idx] = acc;
}

// eigh(BM) -> Q = BM^{1/2}, S = BM^{-1/2}
__global__ __launch_bounds__(32) void k_phaseB(){
  __shared__ __align__(16) float sh[SH_PER_WARP];
  int c = blockIdx.x, lane = threadIdx.x;
  float a[32], vr[32], w[32], o[32];
#pragma unroll
  for(int i=0;i<32;i++) a[i] = g_BM[c*1024 + i*32 + lane];
  float lam = jacobi_vf<MAXSW_SMALL>(a, lane, TOLP_SMALL);
  float sq  = sqrtf(fmaxf(lam, EIG_EPS));
  transp32(vr, a, sh, lane);
#pragma unroll
  for(int i=0;i<32;i++) w[i] = a[i]*sq;
  mm32(o, w, vr, sh, lane);
#pragma unroll
  for(int i=0;i<32;i++) g_Q[c*1024+i*32+lane] = o[i];
  float isq = 1.f/sq;
#pragma unroll
  for(int i=0;i<32;i++) w[i] = a[i]*isq;
  mm32(o, w, vr, sh, lane);
#pragma unroll
  for(int i=0;i<32;i++) g_S[c*1024+i*32+lane] = o[i];
}

// per (b,c): Y = S X S; eigh; cache V; XT = V log(l) V^T; store XT + sum(log^2 l)
__global__ __launch_bounds__(WPB*32,6) void k_phaseC(const float* __restrict__ X){
  extern __shared__ __align__(16) float dsh[];
  int warp = threadIdx.x >> 5, lane = threadIdx.x & 31;
  float* sh = dsh + warp*SH_PER_WARP;
  int task = blockIdx.x*WPB + warp;
  int c = task % Cn;
  float x[32], s[32];
  const float* xp = X + (size_t)task*1024;
#pragma unroll
  for(int i=0;i<32;i++) s[i] = g_S[c*1024+i*32+lane];
  mm32_bg(x, s, xp, sh, lane);              // S*X
  mm32(x, x, s, sh, lane);                  // (S X) S
  float lam = jacobi_vf<MAXSW_BIG>(x, lane, TOLP_BIG); // x -> V
  float lg  = logf(fmaxf(lam, EIG_EPS));
  float sl2 = warp_sum(lg*lg);
  if(lane==0) g_SL2[task] = sl2;
  float* vp = g_V + (size_t)task*1024;
#pragma unroll
  for(int i=0;i<32;i++) vp[i*32+lane] = x[i];   // cache V for phase F
  transp32(s, x, sh, lane);                 // rows of V
#pragma unroll
  for(int i=0;i<32;i++) x[i] *= lg;         // V diag(log l)
  mm32(x, x, s, sh, lane);                  // XT
  float* op = g_XT + (size_t)task*1024;
#pragma unroll
  for(int i=0;i<32;i++) op[i*32+lane] = x[i];
}

__global__ void k_reduce1(){
  int idx = blockIdx.x*blockDim.x + threadIdx.x;
  int s   = blockIdx.y;
  float4 acc = make_float4(0.f,0.f,0.f,0.f);
  const float4* p = reinterpret_cast<const float4*>(g_XT) + (size_t)(s*32)*(Cn*256) + idx;
#pragma unroll 4
  for(int b=0;b<32;b++){
    float4 v = p[(size_t)b*(Cn*256)];
    acc.x += v.x; acc.y += v.y; acc.z += v.z; acc.w += v.w;
  }
  g_P[s*(Cn*256)+idx] = acc;
}

__global__ void k_reduce2(){
  int idx = blockIdx.x*blockDim.x + threadIdx.x;
  float4 acc = make_float4(0.f,0.f,0.f,0.f);
#pragma unroll
  for(int s=0;s<8;s++){
    float4 v = g_P[s*(Cn*256)+idx];
    acc.x += v.x; acc.y += v.y; acc.z += v.z; acc.w += v.w;
  }
  const float sc = 1.f/Bn;
  acc.x*=sc; acc.y*=sc; acc.z*=sc; acc.w*=sc;
  reinterpret_cast<float4*>(g_GT)[idx] = acc;
}

// ETA==1 collapse: rm = BM2 = Q expm(GT) Q, GT_rm = GT.
// AIS = BM2^{-1/2}, MSQ = BM2^{(1-t)/2}, SCALE = std/sqrt(var+eps),
// var = mean||XT||^2 - ||GT||^2.
__global__ __launch_bounds__(32) void k_chan(const float* __restrict__ std_,
                                             const float* __restrict__ pt){
  __shared__ __align__(16) float sh[SH_PER_WARP];
  int c = blockIdx.x, lane = threadIdx.x;
  float a[32], vr[32], w[32], t[32], q[32];
  float f2 = 0.f;
#pragma unroll
  for(int i=0;i<32;i++){ a[i] = g_GT[c*1024+i*32+lane]; f2 = fmaf(a[i],a[i],f2); }
  f2 = warp_sum(f2);                     // ||GT||_F^2
  float shift = sqrtf(f2) + 1.f;
#pragma unroll
  for(int i=0;i<32;i++) a[i] += (i==lane) ? shift : 0.f;
  float lam = jacobi_vf<MAXSW_SMALL>(a, lane, TOLP_SMALL);
  float e = expf(lam - shift);
  transp32(vr, a, sh, lane);
#pragma unroll
  for(int i=0;i<32;i++) w[i] = a[i]*e;
  mm32(t, w, vr, sh, lane);              // expm(GT)
#pragma unroll
  for(int i=0;i<32;i++) q[i] = g_Q[c*1024+i*32+lane];
  mm32(w, q, t, sh, lane);
  mm32(t, w, q, sh, lane);               // BM2
  float lam2 = jacobi_vf<MAXSW_SMALL>(t, lane, TOLP_SMALL);   // t -> V of BM2
  float mu   = fmaxf(lam2, EIG_EPS);
  transp32(vr, t, sh, lane);
#pragma unroll
  for(int i=0;i<32;i++) w[i] = t[i]*rsqrtf(mu);
  mm32(q, w, vr, sh, lane);
#pragma unroll
  for(int i=0;i<32;i++) g_AIS[c*1024+i*32+lane] = q[i];
  float me = expf(0.5f*(1.f - pt[0])*logf(mu));
#pragma unroll
  for(int i=0;i<32;i++) w[i] = t[i]*me;
  mm32(q, w, vr, sh, lane);
#pragma unroll
  for(int i=0;i<32;i++) g_MSQ[c*1024+i*32+lane] = q[i];
  float psl = 0.f;
  for(int b=lane;b<Bn;b+=32) psl += g_SL2[b*Cn + c];
  float msl2 = warp_sum(psl) * (1.f/Bn);
  float bv = msl2 - f2;
  float sc = std_[c] * rsqrtf(bv + EPS_BN);
  if(lane==0) g_SCALE[c] = sc;
}

// per (b,c): warm-started eigh of Z = AIS X AIS using cached V from phase C:
// W = (AIS V)^T X (AIS V) is nearly diagonal -> few sweeps.
// Xn = G G^T, G = MSQ (V Vw) diag(l^{s/2})
__global__ __launch_bounds__(WPB*32,6) void k_phaseF(const float* __restrict__ X,
                                                     float* __restrict__ out){
  extern __shared__ __align__(16) float dsh[];
  int warp = threadIdx.x >> 5, lane = threadIdx.x & 31;
  float* sh = dsh + warp*SH_PER_WARP;
  int task = blockIdx.x*WPB + warp;
  int c = task % Cn;
  float v[32], p[32], t[32], w[32];
  const float* xp = X + (size_t)task*1024;
  const float* vp = g_V + (size_t)task*1024;
#pragma unroll
  for(int i=0;i<32;i++) v[i] = vp[i*32+lane];       // V (cols)
#pragma unroll
  for(int i=0;i<32;i++) t[i] = g_AIS[c*1024+i*32+lane];
  mm32(p, t, v, sh, lane);                 // P = AIS * V
  transp32(t, p, sh, lane);                // Pt
  mm32_bg(t, t, xp, sh, lane);             // Pt * X
  mm32(w, t, p, sh, lane);                 // W = Pt X P  (near diagonal)
  float lam = jacobi_vf<MAXSW_BIG>(w, lane, TOLP_BIG);  // w -> Vw
  float sc  = g_SCALE[c];
  float sd  = expf(0.5f*sc * logf(fmaxf(lam, EIG_EPS)));  // lambda^{s/2}
#pragma unroll
  for(int i=0;i<32;i++) t[i] = g_MSQ[c*1024+i*32+lane];
  mm32(v, t, v, sh, lane);                 // H = MSQ * V
  mm32(w, v, w, sh, lane);                 // G0 = H * Vw
#pragma unroll
  for(int i=0;i<32;i++) w[i] *= sd;        // G
  transp32(v, w, sh, lane);                // rows of G
  mm32(p, w, v, sh, lane);                 // G G^T
  float* op = out + (size_t)task*1024;
#pragma unroll
  for(int i=0;i<32;i++) op[i*32+lane] = p[i];
}

// ================= launcher =================
extern "C" void kernel_launch(void* const* d_in, const int* in_sizes, int n_in,
                              void* d_out, int out_size){
  const float* X     = (const float*)d_in[0];
  const float* std_  = (const float*)d_in[1];
  const float* pt    = (const float*)d_in[4];
  float* out = (float*)d_out;

  cudaFuncSetAttribute(k_phaseC, cudaFuncAttributeMaxDynamicSharedMemorySize, SMEM_BYTES);
  cudaFuncSetAttribute(k_phaseF, cudaFuncAttributeMaxDynamicSharedMemorySize, SMEM_BYTES);

  const int nblk = (Bn*Cn)/WPB;   // 2560 blocks of 4 warps

  k_mean1  <<<dim3(Cn, 8), 256>>>((const float4*)X);
  k_mean2  <<<Cn, 256>>>();
  k_phaseB <<<Cn, 32>>>();
  k_phaseC <<<nblk, WPB*32, SMEM_BYTES>>>(X);
  k_reduce1<<<dim3(Cn, 8), 256>>>();
  k_reduce2<<<Cn, 256>>>();
  k_chan   <<<Cn, 32>>>(std_, pt);
  k_phaseF <<<nblk, WPB*32, SMEM_BYTES>>>(X, out);
}

// round 15
// speedup vs baseline: 1.1316x; 1.0686x over previous
#include <cuda_runtime.h>
#include <cstdint>

#define FULLMASK 0xffffffffu
constexpr int Bn = 256;
constexpr int Cn = 40;
constexpr int MAXSW_BIG   = 10;
constexpr int MAXSW_SMALL = 14;
constexpr float TOL_SKIP   = 1e-10f;  // per-step rotation-skip threshold
constexpr float TOLP_BIG   = 1e-6f;   // predictive sweep-termination tolerance
constexpr float TOLP_SMALL = 1e-8f;
constexpr float EPS_BN  = 1e-5f;
constexpr float EIG_EPS = 1e-6f;
constexpr int WPB = 4;   // 128-thread blocks
// per-warp smem: A panel (36*32, float4 rows) + B panel (33*32, padded rows)
constexpr int SH_PER_WARP = 36*32 + 33*32;   // 2208 floats = 8832 B
constexpr int SMEM_BYTES  = WPB * SH_PER_WARP * 4;   // 35328 B

// ---------------- device scratch ----------------
__device__ __align__(16) float g_BM [Cn*1024];
__device__ __align__(16) float g_S  [Cn*1024];   // BM^{-1/2}
__device__ __align__(16) float g_Q  [Cn*1024];   // BM^{1/2}
__device__ __align__(16) float g_AIS[Cn*1024];   // BM2^{-1/2}
__device__ __align__(16) float g_MSQ[Cn*1024];   // BM2^{(1-t)/2}
__device__ __align__(16) float g_GT [Cn*1024];
__device__ float g_SCALE[Cn];
__device__ float g_SL2[Bn*Cn];
__device__ __align__(16) float g_XT[(size_t)Bn*Cn*1024];   // 41.9 MB
__device__ __align__(16) float g_V [(size_t)Bn*Cn*1024];   // 41.9 MB eigenvector cache
__device__ float4 g_P[8*Cn*256];

// ---------------- helpers ----------------
__device__ __forceinline__ float warp_sum(float v){
#pragma unroll
  for(int o=16;o>0;o>>=1) v += __shfl_xor_sync(FULLMASK, v, o);
  return v;
}

typedef unsigned long long u64;

__device__ __forceinline__ u64 pk2(float lo, float hi){
  u64 r; asm("mov.b64 %0, {%1,%2};" : "=l"(r) : "f"(lo), "f"(hi)); return r;
}
__device__ __forceinline__ void upk2(float& lo, float& hi, u64 v){
  asm("mov.b64 {%0,%1}, %2;" : "=f"(lo), "=f"(hi) : "l"(v));
}
__device__ __forceinline__ u64 ffma2(u64 a, u64 b, u64 c){
  u64 d; asm("fma.rn.f32x2 %0, %1, %2, %3;" : "=l"(d) : "l"(a), "l"(b), "l"(c));
  return d;
}
__device__ __forceinline__ u64 fmul2(u64 a, u64 b){
  u64 d; asm("mul.rn.f32x2 %0, %1, %2;" : "=l"(d) : "l"(a), "l"(b));
  return d;
}
__device__ __forceinline__ u64 fadd2(u64 a, u64 b){
  u64 d; asm("add.rn.f32x2 %0, %1, %2;" : "=l"(d) : "l"(a), "l"(b));
  return d;
}

__device__ __forceinline__ void packv(u64* A, const float* a){
#pragma unroll
  for(int i=0;i<16;i++) A[i] = pk2(a[2*i], a[2*i+1]);
}
__device__ __forceinline__ void unpackv(float* a, const u64* A){
#pragma unroll
  for(int i=0;i<16;i++) upk2(a[2*i], a[2*i+1], A[i]);
}

// ---- matmul variants (column-per-lane register matrices) ----

// staging of A panel (col-major, stride 36, float4 rows)
__device__ __forceinline__ void stageA(const float* a, float* shA, int lane){
  float4* dst = reinterpret_cast<float4*>(shA + lane*36);
#pragma unroll
  for(int u=0;u<8;u++) dst[u] = make_float4(a[4*u],a[4*u+1],a[4*u+2],a[4*u+3]);
}

// shared FMA core over staged shA; bk supplied per-k by the caller lambda-free:
// implemented inline in each variant for clean codegen.

// out = A*B. B staged with B[i][lane] at shB[i*33+lane]; read shB[k*33+lane].
__device__ __forceinline__ void mm32(float* out, const float* a, const float* b,
                                     float* sh, int lane){
  float* shA = sh;
  float* shB = sh + 36*32;
  __syncwarp();
  stageA(a, shA, lane);
#pragma unroll
  for(int i=0;i<32;i++) shB[i*33+lane] = b[i];
  __syncwarp();
  u64 acc[16];
#pragma unroll
  for(int p=0;p<16;p++) acc[p] = 0ull;
#pragma unroll 2
  for(int k=0;k<32;k++){
    float bk = shB[k*33+lane];           // B[k][lane]
    u64 bb = pk2(bk, bk);
    const float4* col = reinterpret_cast<const float4*>(shA + k*36);
#pragma unroll
    for(int u=0;u<8;u++){
      float4 f = col[u];
      acc[2*u]   = ffma2(pk2(f.x, f.y), bb, acc[2*u]);
      acc[2*u+1] = ffma2(pk2(f.z, f.w), bb, acc[2*u+1]);
    }
  }
#pragma unroll
  for(int p=0;p<16;p++) upk2(out[2*p], out[2*p+1], acc[p]);
  __syncwarp();
}

// out = A * B^T. Each lane stages its column of B as a padded ROW:
// shB[lane*33+i] = B[i][lane]. Then B^T[k][lane] = B[lane][k] = shB[k*33+lane].
// (write: fixed i -> addr lane*33+i, stride 33 ≡ 1 mod 32, conflict-free;
//  read: fixed k -> addr k*33+lane, stride 1, conflict-free)
__device__ __forceinline__ void mm32_bt(float* out, const float* a, const float* b,
                                        float* sh, int lane){
  float* shA = sh;
  float* shB = sh + 36*32;
  __syncwarp();
  stageA(a, shA, lane);
#pragma unroll
  for(int i=0;i<32;i++) shB[lane*33+i] = b[i];
  __syncwarp();
  u64 acc[16];
#pragma unroll
  for(int p=0;p<16;p++) acc[p] = 0ull;
#pragma unroll 2
  for(int k=0;k<32;k++){
    float bk = shB[k*33+lane];           // = B[lane][k] = B^T[k][lane]
    u64 bb = pk2(bk, bk);
    const float4* col = reinterpret_cast<const float4*>(shA + k*36);
#pragma unroll
    for(int u=0;u<8;u++){
      float4 f = col[u];
      acc[2*u]   = ffma2(pk2(f.x, f.y), bb, acc[2*u]);
      acc[2*u+1] = ffma2(pk2(f.z, f.w), bb, acc[2*u+1]);
    }
  }
#pragma unroll
  for(int p=0;p<16;p++) upk2(out[2*p], out[2*p+1], acc[p]);
  __syncwarp();
}

// out = A * B with B streamed from global (row-major [i*32+j], 16B aligned).
__device__ __forceinline__ void mm32_bg(float* out, const float* a,
                                        const float* __restrict__ gB,
                                        float* sh, int lane){
  float* shA = sh;
  float* shB = sh + 36*32;
  __syncwarp();
  stageA(a, shA, lane);
  {
    const float4* g4 = reinterpret_cast<const float4*>(gB);
    float4* s4 = reinterpret_cast<float4*>(shB);
#pragma unroll
    for(int u=0;u<8;u++) s4[u*32+lane] = g4[u*32+lane];
  }
  __syncwarp();
  u64 acc[16];
#pragma unroll
  for(int p=0;p<16;p++) acc[p] = 0ull;
#pragma unroll 2
  for(int k=0;k<32;k++){
    float bk = shB[k*32+lane];
    u64 bb = pk2(bk, bk);
    const float4* col = reinterpret_cast<const float4*>(shA + k*36);
#pragma unroll
    for(int u=0;u<8;u++){
      float4 f = col[u];
      acc[2*u]   = ffma2(pk2(f.x, f.y), bb, acc[2*u]);
      acc[2*u+1] = ffma2(pk2(f.z, f.w), bb, acc[2*u+1]);
    }
  }
#pragma unroll
  for(int p=0;p<16;p++) upk2(out[2*p], out[2*p+1], acc[p]);
  __syncwarp();
}

// dst = rows of src (columns of src^T)
__device__ __forceinline__ void transp32(float* dst, const float* src,
                                         float* sh, int lane){
  __syncwarp();
#pragma unroll
  for(int i=0;i<32;i++) sh[i*33+lane] = src[i];
  __syncwarp();
#pragma unroll
  for(int k=0;k<32;k++) dst[k] = sh[lane*33+k];
  __syncwarp();
}

// ---- Jacobi building blocks (f32x2-packed columns) ----

__device__ __forceinline__ float colnorm2(const u64* A){
  u64 na=0ull, nb=0ull;
#pragma unroll
  for(int i=0;i<16;i+=2){ na = ffma2(A[i],A[i],na); nb = ffma2(A[i+1],A[i+1],nb); }
  float xl,xh,yl,yh; upk2(xl,xh,na); upk2(yl,yh,nb);
  return (xl+xh)+(yl+yh);
}

// gamma/beta/scalars shared by both step variants
#define JSTEP_PRE                                                        \
  u64 Bv[16];                                                            \
  u64 q0=0ull, q1=0ull, q2=0ull, q3=0ull;                                \
  _Pragma("unroll")                                                      \
  for(int i=0;i<16;i+=4){                                                \
    Bv[i]   = __shfl_xor_sync(FULLMASK, A[i],   r);                      \
    Bv[i+1] = __shfl_xor_sync(FULLMASK, A[i+1], r);                      \
    Bv[i+2] = __shfl_xor_sync(FULLMASK, A[i+2], r);                      \
    Bv[i+3] = __shfl_xor_sync(FULLMASK, A[i+3], r);                      \
    q0 = ffma2(A[i],  Bv[i],  q0);                                       \
    q1 = ffma2(A[i+1],Bv[i+1],q1);                                       \
    q2 = ffma2(A[i+2],Bv[i+2],q2);                                       \
    q3 = ffma2(A[i+3],Bv[i+3],q3);                                       \
  }                                                                      \
  u64 qc = fadd2(fadd2(q0,q1), fadd2(q2,q3));                            \
  float xl,xh; upk2(xl,xh,qc);                                           \
  float gamma = xl+xh;                                                   \
  float beta  = __shfl_xor_sync(FULLMASK, alpha, r);                     \
  bool  isp   = lane < (lane ^ r);                                       \
  float app   = isp ? alpha : beta;                                      \
  float aqq   = isp ? beta  : alpha;                                     \
  float gg    = gamma*gamma;                                             \
  float dd    = app*aqq;                                                 \
  float d    = aqq - app;                                                \
  float g2   = gamma + gamma;                                            \
  float rh   = rsqrtf(fmaf(d,d, g2*g2));                                 \
  float cos2 = fabsf(d)*rh;                                              \
  float c2   = fmaf(0.5f, cos2, 0.5f);                                   \
  float rc   = rsqrtf(c2);                                               \
  float c0   = c2*rc;                                                    \
  float sgn  = copysignf(1.f, d);                                        \
  float s0   = gamma*sgn*rh*rc;                                          \
  float t0   = s0*rc;                                                    \
  bool  rot  = gg > 1e-28f*dd;                                           \
  float c = rot ? c0 : 1.f;                                              \
  float s = rot ? s0 : 0.f;                                              \
  float t = rot ? t0 : 0.f;

#define JSTEP_APPLY                                                      \
  float se = isp ? -s : s;                                               \
  float te = isp ? -t : t;                                               \
  u64 C2 = pk2(c,c), S2 = pk2(se,se);                                    \
  _Pragma("unroll")                                                      \
  for(int i=0;i<16;i++) A[i] = ffma2(S2, Bv[i], fmul2(C2, A[i]));        \
  alpha = fmaf(te, gamma, alpha);

// voteless unconditional step (early sweeps: nothing ever skips)
__device__ __forceinline__ void jstep_nv(u64* A, float& alpha, int r, int lane){
  JSTEP_PRE
  JSTEP_APPLY
}

// voted step (late sweeps): skip rotation when whole warp is converged;
// conv accumulates the looser predictive-termination predicate.
__device__ __forceinline__ void jstep(u64* A, float& alpha, bool& conv,
                                      int r, int lane, float tolp){
  JSTEP_PRE
  bool skipc = gg <= TOL_SKIP*dd;
  conv = conv && (gg <= tolp*dd);
  if(!__all_sync(FULLMASK, skipc)){
    JSTEP_APPLY
  }
}

__device__ __forceinline__ float jfinish(u64* A){
  float nn  = colnorm2(A);
  float inv = rsqrtf(nn);
  u64 I2 = pk2(inv,inv);
#pragma unroll
  for(int i=0;i<16;i++) A[i] = fmul2(I2, A[i]);
  return nn*inv;   // sqrt(nn) = eigenvalue (SPD)
}

// One-sided Jacobi: NVSWEEP voteless sweeps, then voted sweeps with
// per-step skip and predictive termination.
template<int MAXSWEEP, int NVSWEEP>
__device__ __forceinline__ float jacobi_vf(float* a, int lane, float tolp){
  u64 A[16];
  packv(A, a);
#pragma unroll 1
  for(int sw=0; sw<NVSWEEP; ++sw){
    float alpha = colnorm2(A);
#pragma unroll 1
    for(int r=1;r<32;r++) jstep_nv(A, alpha, r, lane);
  }
#pragma unroll 1
  for(int sw=NVSWEEP; sw<MAXSWEEP; ++sw){
    float alpha = colnorm2(A);
    bool conv = true;
#pragma unroll 1
    for(int r=1;r<32;r++) jstep(A, alpha, conv, r, lane, tolp);
    if(__all_sync(FULLMASK, conv)) break;
  }
  float lam = jfinish(A);
  unpackv(a, A);
  return lam;
}

// ================= kernels =================

__global__ void k_mean1(const float4* __restrict__ X4){
  int idx = blockIdx.x*blockDim.x + threadIdx.x;
  int s   = blockIdx.y;
  float4 acc = make_float4(0.f,0.f,0.f,0.f);
  const float4* p = X4 + (size_t)(s*32)*(Cn*256) + idx;
#pragma unroll 4
  for(int b=0;b<32;b++){
    float4 v = p[(size_t)b*(Cn*256)];
    acc.x += v.x; acc.y += v.y; acc.z += v.z; acc.w += v.w;
  }
  g_P[s*(Cn*256)+idx] = acc;
}

__global__ void k_mean2(){
  int idx = blockIdx.x*blockDim.x + threadIdx.x;
  float4 acc = make_float4(0.f,0.f,0.f,0.f);
#pragma unroll
  for(int s=0;s<8;s++){
    float4 v = g_P[s*(Cn*256)+idx];
    acc.x += v.x; acc.y += v.y; acc.z += v.z; acc.w += v.w;
  }
  const float sc = 1.f/Bn;
  acc.x*=sc; acc.y*=sc; acc.z*=sc; acc.w*=sc;
  reinterpret_cast<float4*>(g_BM)[idx] = acc;
}

// eigh(BM) -> Q = BM^{1/2}, S = BM^{-1/2}
__global__ __launch_bounds__(32) void k_phaseB(){
  __shared__ __align__(16) float sh[SH_PER_WARP];
  int c = blockIdx.x, lane = threadIdx.x;
  float a[32], w[32], o[32];
#pragma unroll
  for(int i=0;i<32;i++) a[i] = g_BM[c*1024 + i*32 + lane];
  float lam = jacobi_vf<MAXSW_SMALL,3>(a, lane, TOLP_SMALL);
  float sq  = sqrtf(fmaxf(lam, EIG_EPS));
#pragma unroll
  for(int i=0;i<32;i++) w[i] = a[i]*sq;
  mm32_bt(o, w, a, sh, lane);              // (V sq) V^T
#pragma unroll
  for(int i=0;i<32;i++) g_Q[c*1024+i*32+lane] = o[i];
  float isq = 1.f/sq;
#pragma unroll
  for(int i=0;i<32;i++) w[i] = a[i]*isq;
  mm32_bt(o, w, a, sh, lane);
#pragma unroll
  for(int i=0;i<32;i++) g_S[c*1024+i*32+lane] = o[i];
}

// per (b,c): Y = S X S; eigh; cache V; XT = V log(l) V^T; store XT + sum(log^2 l)
__global__ __launch_bounds__(WPB*32,6) void k_phaseC(const float* __restrict__ X){
  extern __shared__ __align__(16) float dsh[];
  int warp = threadIdx.x >> 5, lane = threadIdx.x & 31;
  float* sh = dsh + warp*SH_PER_WARP;
  int task = blockIdx.x*WPB + warp;
  int c = task % Cn;
  float x[32], s[32];
  const float* xp = X + (size_t)task*1024;
#pragma unroll
  for(int i=0;i<32;i++) s[i] = g_S[c*1024+i*32+lane];
  mm32_bg(x, s, xp, sh, lane);              // S*X
  mm32(x, x, s, sh, lane);                  // (S X) S
  float lam = jacobi_vf<MAXSW_BIG,3>(x, lane, TOLP_BIG); // x -> V
  float lg  = logf(fmaxf(lam, EIG_EPS));
  float sl2 = warp_sum(lg*lg);
  if(lane==0) g_SL2[task] = sl2;
  float* vp = g_V + (size_t)task*1024;
#pragma unroll
  for(int i=0;i<32;i++) vp[i*32+lane] = x[i];   // cache V for phase F
#pragma unroll
  for(int i=0;i<32;i++) s[i] = x[i]*lg;     // V diag(log l)
  mm32_bt(x, s, x, sh, lane);               // XT = (V lg) V^T
  float* op = g_XT + (size_t)task*1024;
#pragma unroll
  for(int i=0;i<32;i++) op[i*32+lane] = x[i];
}

__global__ void k_reduce1(){
  int idx = blockIdx.x*blockDim.x + threadIdx.x;
  int s   = blockIdx.y;
  float4 acc = make_float4(0.f,0.f,0.f,0.f);
  const float4* p = reinterpret_cast<const float4*>(g_XT) + (size_t)(s*32)*(Cn*256) + idx;
#pragma unroll 4
  for(int b=0;b<32;b++){
    float4 v = p[(size_t)b*(Cn*256)];
    acc.x += v.x; acc.y += v.y; acc.z += v.z; acc.w += v.w;
  }
  g_P[s*(Cn*256)+idx] = acc;
}

__global__ void k_reduce2(){
  int idx = blockIdx.x*blockDim.x + threadIdx.x;
  float4 acc = make_float4(0.f,0.f,0.f,0.f);
#pragma unroll
  for(int s=0;s<8;s++){
    float4 v = g_P[s*(Cn*256)+idx];
    acc.x += v.x; acc.y += v.y; acc.z += v.z; acc.w += v.w;
  }
  const float sc = 1.f/Bn;
  acc.x*=sc; acc.y*=sc; acc.z*=sc; acc.w*=sc;
  reinterpret_cast<float4*>(g_GT)[idx] = acc;
}

// ETA==1 collapse: rm = BM2 = Q expm(GT) Q, GT_rm = GT.
// AIS = BM2^{-1/2}, MSQ = BM2^{(1-t)/2}, SCALE = std/sqrt(var+eps),
// var = mean||XT||^2 - ||GT||^2.
__global__ __launch_bounds__(32) void k_chan(const float* __restrict__ std_,
                                             const float* __restrict__ pt){
  __shared__ __align__(16) float sh[SH_PER_WARP];
  int c = blockIdx.x, lane = threadIdx.x;
  float a[32], w[32], t[32], q[32];
  float f2 = 0.f;
#pragma unroll
  for(int i=0;i<32;i++){ a[i] = g_GT[c*1024+i*32+lane]; f2 = fmaf(a[i],a[i],f2); }
  f2 = warp_sum(f2);                     // ||GT||_F^2
  float shift = sqrtf(f2) + 1.f;
#pragma unroll
  for(int i=0;i<32;i++) a[i] += (i==lane) ? shift : 0.f;
  float lam = jacobi_vf<MAXSW_SMALL,3>(a, lane, TOLP_SMALL);
  float e = expf(lam - shift);
#pragma unroll
  for(int i=0;i<32;i++) w[i] = a[i]*e;
  mm32_bt(t, w, a, sh, lane);            // expm(GT)
#pragma unroll
  for(int i=0;i<32;i++) q[i] = g_Q[c*1024+i*32+lane];
  mm32(w, q, t, sh, lane);
  mm32(t, w, q, sh, lane);               // BM2
  float lam2 = jacobi_vf<MAXSW_SMALL,3>(t, lane, TOLP_SMALL);   // t -> V of BM2
  float mu   = fmaxf(lam2, EIG_EPS);
#pragma unroll
  for(int i=0;i<32;i++) w[i] = t[i]*rsqrtf(mu);
  mm32_bt(q, w, t, sh, lane);
#pragma unroll
  for(int i=0;i<32;i++) g_AIS[c*1024+i*32+lane] = q[i];
  float me = expf(0.5f*(1.f - pt[0])*logf(mu));
#pragma unroll
  for(int i=0;i<32;i++) w[i] = t[i]*me;
  mm32_bt(q, w, t, sh, lane);
#pragma unroll
  for(int i=0;i<32;i++) g_MSQ[c*1024+i*32+lane] = q[i];
  float psl = 0.f;
  for(int b=lane;b<Bn;b+=32) psl += g_SL2[b*Cn + c];
  float msl2 = warp_sum(psl) * (1.f/Bn);
  float bv = msl2 - f2;
  float sc = std_[c] * rsqrtf(bv + EPS_BN);
  if(lane==0) g_SCALE[c] = sc;
}

// per (b,c): warm-started eigh of Z = AIS X AIS using cached V from phase C:
// W = (AIS V)^T X (AIS V) is nearly diagonal -> few sweeps (NV=1).
// Xn = G G^T, G = MSQ (V Vw) diag(l^{s/2})
__global__ __launch_bounds__(WPB*32,6) void k_phaseF(const float* __restrict__ X,
                                                     float* __restrict__ out){
  extern __shared__ __align__(16) float dsh[];
  int warp = threadIdx.x >> 5, lane = threadIdx.x & 31;
  float* sh = dsh + warp*SH_PER_WARP;
  int task = blockIdx.x*WPB + warp;
  int c = task % Cn;
  float v[32], p[32], t[32], w[32];
  const float* xp = X + (size_t)task*1024;
  const float* vp = g_V + (size_t)task*1024;
#pragma unroll
  for(int i=0;i<32;i++) v[i] = vp[i*32+lane];       // V (cols)
#pragma unroll
  for(int i=0;i<32;i++) t[i] = g_AIS[c*1024+i*32+lane];
  mm32(p, t, v, sh, lane);                 // P = AIS * V
  transp32(t, p, sh, lane);                // Pt
  mm32_bg(t, t, xp, sh, lane);             // Pt * X
  mm32(w, t, p, sh, lane);                 // W = Pt X P  (near diagonal)
  float lam = jacobi_vf<MAXSW_BIG,1>(w, lane, TOLP_BIG);  // w -> Vw
  float sc  = g_SCALE[c];
  float sd  = expf(0.5f*sc * logf(fmaxf(lam, EIG_EPS)));  // lambda^{s/2}
#pragma unroll
  for(int i=0;i<32;i++) t[i] = g_MSQ[c*1024+i*32+lane];
  mm32(v, t, v, sh, lane);                 // H = MSQ * V
  mm32(w, v, w, sh, lane);                 // G0 = H * Vw
#pragma unroll
  for(int i=0;i<32;i++) w[i] *= sd;        // G
  mm32_bt(p, w, w, sh, lane);              // G G^T
  float* op = out + (size_t)task*1024;
#pragma unroll
  for(int i=0;i<32;i++) op[i*32+lane] = p[i];
}

// ================= launcher =================
extern "C" void kernel_launch(void* const* d_in, const int* in_sizes, int n_in,
                              void* d_out, int out_size){
  const float* X     = (const float*)d_in[0];
  const float* std_  = (const float*)d_in[1];
  const float* pt    = (const float*)d_in[4];
  float* out = (float*)d_out;

  cudaFuncSetAttribute(k_phaseC, cudaFuncAttributeMaxDynamicSharedMemorySize, SMEM_BYTES);
  cudaFuncSetAttribute(k_phaseF, cudaFuncAttributeMaxDynamicSharedMemorySize, SMEM_BYTES);

  const int nblk = (Bn*Cn)/WPB;   // 2560 blocks of 4 warps

  k_mean1  <<<dim3(Cn, 8), 256>>>((const float4*)X);
  k_mean2  <<<Cn, 256>>>();
  k_phaseB <<<Cn, 32>>>();
  k_phaseC <<<nblk, WPB*32, SMEM_BYTES>>>(X);
  k_reduce1<<<dim3(Cn, 8), 256>>>();
  k_reduce2<<<Cn, 256>>>();
  k_chan   <<<Cn, 32>>>(std_, pt);
  k_phaseF <<<nblk, WPB*32, SMEM_BYTES>>>(X, out);
}

// round 16
// speedup vs baseline: 1.1393x; 1.0068x over previous
#include <cuda_runtime.h>
#include <cstdint>

#define FULLMASK 0xffffffffu
constexpr int Bn = 256;
constexpr int Cn = 40;
constexpr int MAXSW_BIG   = 10;
constexpr int MAXSW_SMALL = 14;
constexpr int NSLICE = 16;            // stage-1 reduction slices
constexpr float TOL_SKIP   = 1e-10f;  // per-step rotation-skip threshold
constexpr float TOLP_BIG   = 1e-6f;   // predictive sweep-termination tolerance
constexpr float TOLP_SMALL = 1e-8f;
constexpr float EPS_BN  = 1e-5f;
constexpr float EIG_EPS = 1e-6f;
constexpr int WPB = 4;   // 128-thread blocks
// per-warp smem: A panel (36*32, float4 rows) + B panel (33*32, padded rows)
constexpr int SH_PER_WARP = 36*32 + 33*32;   // 2208 floats = 8832 B
constexpr int SMEM_BYTES  = WPB * SH_PER_WARP * 4;   // 35328 B

// ---------------- device scratch ----------------
__device__ __align__(16) float g_S  [Cn*1024];   // BM^{-1/2}
__device__ __align__(16) float g_Q  [Cn*1024];   // BM^{1/2}
__device__ __align__(16) float g_AIS[Cn*1024];   // BM2^{-1/2}
__device__ __align__(16) float g_MSQ[Cn*1024];   // BM2^{(1-t)/2}
__device__ float g_SCALE[Cn];
__device__ float g_SL2[Bn*Cn];
__device__ __align__(16) float g_XT[(size_t)Bn*Cn*1024];   // 41.9 MB
__device__ __align__(16) float g_V [(size_t)Bn*Cn*1024];   // 41.9 MB eigenvector cache
__device__ float4 g_P[NSLICE*Cn*256];                      // stage-1 partials

// ---------------- helpers ----------------
__device__ __forceinline__ float warp_sum(float v){
#pragma unroll
  for(int o=16;o>0;o>>=1) v += __shfl_xor_sync(FULLMASK, v, o);
  return v;
}

typedef unsigned long long u64;

__device__ __forceinline__ u64 pk2(float lo, float hi){
  u64 r; asm("mov.b64 %0, {%1,%2};" : "=l"(r) : "f"(lo), "f"(hi)); return r;
}
__device__ __forceinline__ void upk2(float& lo, float& hi, u64 v){
  asm("mov.b64 {%0,%1}, %2;" : "=f"(lo), "=f"(hi) : "l"(v));
}
__device__ __forceinline__ u64 ffma2(u64 a, u64 b, u64 c){
  u64 d; asm("fma.rn.f32x2 %0, %1, %2, %3;" : "=l"(d) : "l"(a), "l"(b), "l"(c));
  return d;
}
__device__ __forceinline__ u64 fmul2(u64 a, u64 b){
  u64 d; asm("mul.rn.f32x2 %0, %1, %2;" : "=l"(d) : "l"(a), "l"(b));
  return d;
}
__device__ __forceinline__ u64 fadd2(u64 a, u64 b){
  u64 d; asm("add.rn.f32x2 %0, %1, %2;" : "=l"(d) : "l"(a), "l"(b));
  return d;
}

__device__ __forceinline__ void packv(u64* A, const float* a){
#pragma unroll
  for(int i=0;i<16;i++) A[i] = pk2(a[2*i], a[2*i+1]);
}
__device__ __forceinline__ void unpackv(float* a, const u64* A){
#pragma unroll
  for(int i=0;i<16;i++) upk2(a[2*i], a[2*i+1], A[i]);
}

// ---- matmul variants (column-per-lane register matrices) ----

__device__ __forceinline__ void stageA(const float* a, float* shA, int lane){
  float4* dst = reinterpret_cast<float4*>(shA + lane*36);
#pragma unroll
  for(int u=0;u<8;u++) dst[u] = make_float4(a[4*u],a[4*u+1],a[4*u+2],a[4*u+3]);
}

// out = A*B. B staged with B[i][lane] at shB[i*33+lane]; read shB[k*33+lane].
__device__ __forceinline__ void mm32(float* out, const float* a, const float* b,
                                     float* sh, int lane){
  float* shA = sh;
  float* shB = sh + 36*32;
  __syncwarp();
  stageA(a, shA, lane);
#pragma unroll
  for(int i=0;i<32;i++) shB[i*33+lane] = b[i];
  __syncwarp();
  u64 acc[16];
#pragma unroll
  for(int p=0;p<16;p++) acc[p] = 0ull;
#pragma unroll 2
  for(int k=0;k<32;k++){
    float bk = shB[k*33+lane];           // B[k][lane]
    u64 bb = pk2(bk, bk);
    const float4* col = reinterpret_cast<const float4*>(shA + k*36);
#pragma unroll
    for(int u=0;u<8;u++){
      float4 f = col[u];
      acc[2*u]   = ffma2(pk2(f.x, f.y), bb, acc[2*u]);
      acc[2*u+1] = ffma2(pk2(f.z, f.w), bb, acc[2*u+1]);
    }
  }
#pragma unroll
  for(int p=0;p<16;p++) upk2(out[2*p], out[2*p+1], acc[p]);
  __syncwarp();
}

// out = A * B^T. Lane stages its column of B as a padded ROW: shB[lane*33+i]=B[i][lane].
// Read shB[k*33+lane] = B[lane][k] = B^T[k][lane]. Conflict-free both directions.
__device__ __forceinline__ void mm32_bt(float* out, const float* a, const float* b,
                                        float* sh, int lane){
  float* shA = sh;
  float* shB = sh + 36*32;
  __syncwarp();
  stageA(a, shA, lane);
#pragma unroll
  for(int i=0;i<32;i++) shB[lane*33+i] = b[i];
  __syncwarp();
  u64 acc[16];
#pragma unroll
  for(int p=0;p<16;p++) acc[p] = 0ull;
#pragma unroll 2
  for(int k=0;k<32;k++){
    float bk = shB[k*33+lane];           // B^T[k][lane]
    u64 bb = pk2(bk, bk);
    const float4* col = reinterpret_cast<const float4*>(shA + k*36);
#pragma unroll
    for(int u=0;u<8;u++){
      float4 f = col[u];
      acc[2*u]   = ffma2(pk2(f.x, f.y), bb, acc[2*u]);
      acc[2*u+1] = ffma2(pk2(f.z, f.w), bb, acc[2*u+1]);
    }
  }
#pragma unroll
  for(int p=0;p<16;p++) upk2(out[2*p], out[2*p+1], acc[p]);
  __syncwarp();
}

// out = A * B with B streamed from global (row-major [i*32+j], 16B aligned).
__device__ __forceinline__ void mm32_bg(float* out, const float* a,
                                        const float* __restrict__ gB,
                                        float* sh, int lane){
  float* shA = sh;
  float* shB = sh + 36*32;
  __syncwarp();
  stageA(a, shA, lane);
  {
    const float4* g4 = reinterpret_cast<const float4*>(gB);
    float4* s4 = reinterpret_cast<float4*>(shB);
#pragma unroll
    for(int u=0;u<8;u++) s4[u*32+lane] = g4[u*32+lane];
  }
  __syncwarp();
  u64 acc[16];
#pragma unroll
  for(int p=0;p<16;p++) acc[p] = 0ull;
#pragma unroll 2
  for(int k=0;k<32;k++){
    float bk = shB[k*32+lane];
    u64 bb = pk2(bk, bk);
    const float4* col = reinterpret_cast<const float4*>(shA + k*36);
#pragma unroll
    for(int u=0;u<8;u++){
      float4 f = col[u];
      acc[2*u]   = ffma2(pk2(f.x, f.y), bb, acc[2*u]);
      acc[2*u+1] = ffma2(pk2(f.z, f.w), bb, acc[2*u+1]);
    }
  }
#pragma unroll
  for(int p=0;p<16;p++) upk2(out[2*p], out[2*p+1], acc[p]);
  __syncwarp();
}

// dst = rows of src (columns of src^T)
__device__ __forceinline__ void transp32(float* dst, const float* src,
                                         float* sh, int lane){
  __syncwarp();
#pragma unroll
  for(int i=0;i<32;i++) sh[i*33+lane] = src[i];
  __syncwarp();
#pragma unroll
  for(int k=0;k<32;k++) dst[k] = sh[lane*33+k];
  __syncwarp();
}

// ---- Jacobi building blocks (f32x2-packed columns) ----

__device__ __forceinline__ float colnorm2(const u64* A){
  u64 na=0ull, nb=0ull;
#pragma unroll
  for(int i=0;i<16;i+=2){ na = ffma2(A[i],A[i],na); nb = ffma2(A[i+1],A[i+1],nb); }
  float xl,xh,yl,yh; upk2(xl,xh,na); upk2(yl,yh,nb);
  return (xl+xh)+(yl+yh);
}

#define JSTEP_PRE                                                        \
  u64 Bv[16];                                                            \
  u64 q0=0ull, q1=0ull, q2=0ull, q3=0ull;                                \
  _Pragma("unroll")                                                      \
  for(int i=0;i<16;i+=4){                                                \
    Bv[i]   = __shfl_xor_sync(FULLMASK, A[i],   r);                      \
    Bv[i+1] = __shfl_xor_sync(FULLMASK, A[i+1], r);                      \
    Bv[i+2] = __shfl_xor_sync(FULLMASK, A[i+2], r);                      \
    Bv[i+3] = __shfl_xor_sync(FULLMASK, A[i+3], r);                      \
    q0 = ffma2(A[i],  Bv[i],  q0);                                       \
    q1 = ffma2(A[i+1],Bv[i+1],q1);                                       \
    q2 = ffma2(A[i+2],Bv[i+2],q2);                                       \
    q3 = ffma2(A[i+3],Bv[i+3],q3);                                       \
  }                                                                      \
  u64 qc = fadd2(fadd2(q0,q1), fadd2(q2,q3));                            \
  float xl,xh; upk2(xl,xh,qc);                                           \
  float gamma = xl+xh;                                                   \
  float beta  = __shfl_xor_sync(FULLMASK, alpha, r);                     \
  bool  isp   = lane < (lane ^ r);                                       \
  float app   = isp ? alpha : beta;                                      \
  float aqq   = isp ? beta  : alpha;                                     \
  float gg    = gamma*gamma;                                             \
  float dd    = app*aqq;                                                 \
  float d    = aqq - app;                                                \
  float g2   = gamma + gamma;                                            \
  float rh   = rsqrtf(fmaf(d,d, g2*g2));                                 \
  float cos2 = fabsf(d)*rh;                                              \
  float c2   = fmaf(0.5f, cos2, 0.5f);                                   \
  float rc   = rsqrtf(c2);                                               \
  float c0   = c2*rc;                                                    \
  float sgn  = copysignf(1.f, d);                                        \
  float s0   = gamma*sgn*rh*rc;                                          \
  float t0   = s0*rc;                                                    \
  bool  rot  = gg > 1e-28f*dd;                                           \
  float c = rot ? c0 : 1.f;                                              \
  float s = rot ? s0 : 0.f;                                              \
  float t = rot ? t0 : 0.f;

#define JSTEP_APPLY                                                      \
  float se = isp ? -s : s;                                               \
  float te = isp ? -t : t;                                               \
  u64 C2 = pk2(c,c), S2 = pk2(se,se);                                    \
  _Pragma("unroll")                                                      \
  for(int i=0;i<16;i++) A[i] = ffma2(S2, Bv[i], fmul2(C2, A[i]));        \
  alpha = fmaf(te, gamma, alpha);

// voteless unconditional step (early sweeps: nothing ever skips)
__device__ __forceinline__ void jstep_nv(u64* A, float& alpha, int r, int lane){
  JSTEP_PRE
  JSTEP_APPLY
}

// voted step (late sweeps): skip rotation when whole warp is converged;
// conv accumulates the looser predictive-termination predicate.
__device__ __forceinline__ void jstep(u64* A, float& alpha, bool& conv,
                                      int r, int lane, float tolp){
  JSTEP_PRE
  bool skipc = gg <= TOL_SKIP*dd;
  conv = conv && (gg <= tolp*dd);
  if(!__all_sync(FULLMASK, skipc)){
    JSTEP_APPLY
  }
}

__device__ __forceinline__ float jfinish(u64* A){
  float nn  = colnorm2(A);
  float inv = rsqrtf(nn);
  u64 I2 = pk2(inv,inv);
#pragma unroll
  for(int i=0;i<16;i++) A[i] = fmul2(I2, A[i]);
  return nn*inv;   // sqrt(nn) = eigenvalue (SPD)
}

// One-sided Jacobi: NVSWEEP voteless sweeps, then voted sweeps with
// per-step skip and predictive termination.
template<int MAXSWEEP, int NVSWEEP>
__device__ __forceinline__ float jacobi_vf(float* a, int lane, float tolp){
  u64 A[16];
  packv(A, a);
#pragma unroll 1
  for(int sw=0; sw<NVSWEEP; ++sw){
    float alpha = colnorm2(A);
#pragma unroll 1
    for(int r=1;r<32;r++) jstep_nv(A, alpha, r, lane);
  }
#pragma unroll 1
  for(int sw=NVSWEEP; sw<MAXSWEEP; ++sw){
    float alpha = colnorm2(A);
    bool conv = true;
#pragma unroll 1
    for(int r=1;r<32;r++) jstep(A, alpha, conv, r, lane, tolp);
    if(__all_sync(FULLMASK, conv)) break;
  }
  float lam = jfinish(A);
  unpackv(a, A);
  return lam;
}

// ================= kernels =================

// stage-1 mean partials: slice s sums 16 batches
__global__ void k_mean1(const float4* __restrict__ X4){
  int idx = blockIdx.x*blockDim.x + threadIdx.x;
  int s   = blockIdx.y;
  float4 acc = make_float4(0.f,0.f,0.f,0.f);
  const float4* p = X4 + (size_t)(s*(Bn/NSLICE))*(Cn*256) + idx;
#pragma unroll 8
  for(int b=0;b<Bn/NSLICE;b++){
    float4 v = p[(size_t)b*(Cn*256)];
    acc.x += v.x; acc.y += v.y; acc.z += v.z; acc.w += v.w;
  }
  g_P[s*(Cn*256)+idx] = acc;
}

// eigh(BM) -> Q = BM^{1/2}, S = BM^{-1/2}; BM summed from stage-1 partials.
__global__ __launch_bounds__(32) void k_phaseB(){
  __shared__ __align__(16) float sh[SH_PER_WARP];
  int c = blockIdx.x, lane = threadIdx.x;
  float a[32], w[32], o[32];
  const float* gp = reinterpret_cast<const float*>(g_P);
#pragma unroll
  for(int i=0;i<32;i++){
    float acc = 0.f;
#pragma unroll
    for(int s=0;s<NSLICE;s++) acc += gp[(size_t)s*(Cn*1024) + c*1024 + i*32 + lane];
    a[i] = acc * (1.f/Bn);
  }
  float lam = jacobi_vf<MAXSW_SMALL,3>(a, lane, TOLP_SMALL);
  float sq  = sqrtf(fmaxf(lam, EIG_EPS));
#pragma unroll
  for(int i=0;i<32;i++) w[i] = a[i]*sq;
  mm32_bt(o, w, a, sh, lane);              // (V sq) V^T
#pragma unroll
  for(int i=0;i<32;i++) g_Q[c*1024+i*32+lane] = o[i];
  float isq = 1.f/sq;
#pragma unroll
  for(int i=0;i<32;i++) w[i] = a[i]*isq;
  mm32_bt(o, w, a, sh, lane);
#pragma unroll
  for(int i=0;i<32;i++) g_S[c*1024+i*32+lane] = o[i];
}

// per (b,c): Y = S X S; eigh; cache V; XT = V log(l) V^T; store XT + sum(log^2 l)
__global__ __launch_bounds__(WPB*32,6) void k_phaseC(const float* __restrict__ X){
  extern __shared__ __align__(16) float dsh[];
  int warp = threadIdx.x >> 5, lane = threadIdx.x & 31;
  float* sh = dsh + warp*SH_PER_WARP;
  int task = blockIdx.x*WPB + warp;
  int c = task % Cn;
  float x[32], s[32];
  const float* xp = X + (size_t)task*1024;
#pragma unroll
  for(int i=0;i<32;i++) s[i] = g_S[c*1024+i*32+lane];
  mm32_bg(x, s, xp, sh, lane);              // S*X
  mm32(x, x, s, sh, lane);                  // (S X) S
  float lam = jacobi_vf<MAXSW_BIG,4>(x, lane, TOLP_BIG); // x -> V
  float lg  = logf(fmaxf(lam, EIG_EPS));
  float sl2 = warp_sum(lg*lg);
  if(lane==0) g_SL2[task] = sl2;
  float* vp = g_V + (size_t)task*1024;
#pragma unroll
  for(int i=0;i<32;i++) vp[i*32+lane] = x[i];   // cache V for phase F
#pragma unroll
  for(int i=0;i<32;i++) s[i] = x[i]*lg;     // V diag(log l)
  mm32_bt(x, s, x, sh, lane);               // XT = (V lg) V^T
  float* op = g_XT + (size_t)task*1024;
#pragma unroll
  for(int i=0;i<32;i++) op[i*32+lane] = x[i];
}

// stage-1 XT partials
__global__ void k_reduce1(){
  int idx = blockIdx.x*blockDim.x + threadIdx.x;
  int s   = blockIdx.y;
  float4 acc = make_float4(0.f,0.f,0.f,0.f);
  const float4* p = reinterpret_cast<const float4*>(g_XT)
                  + (size_t)(s*(Bn/NSLICE))*(Cn*256) + idx;
#pragma unroll 8
  for(int b=0;b<Bn/NSLICE;b++){
    float4 v = p[(size_t)b*(Cn*256)];
    acc.x += v.x; acc.y += v.y; acc.z += v.z; acc.w += v.w;
  }
  g_P[s*(Cn*256)+idx] = acc;
}

// ETA==1 collapse: rm = BM2 = Q expm(GT) Q, GT_rm = GT.
// AIS = BM2^{-1/2}, MSQ = BM2^{(1-t)/2}, SCALE = std/sqrt(var+eps),
// var = mean||XT||^2 - ||GT||^2.   GT summed from stage-1 partials.
__global__ __launch_bounds__(32) void k_chan(const float* __restrict__ std_,
                                             const float* __restrict__ pt){
  __shared__ __align__(16) float sh[SH_PER_WARP];
  int c = blockIdx.x, lane = threadIdx.x;
  float a[32], w[32], t[32], q[32];
  const float* gp = reinterpret_cast<const float*>(g_P);
  float f2 = 0.f;
#pragma unroll
  for(int i=0;i<32;i++){
    float acc = 0.f;
#pragma unroll
    for(int s=0;s<NSLICE;s++) acc += gp[(size_t)s*(Cn*1024) + c*1024 + i*32 + lane];
    a[i] = acc * (1.f/Bn);
    f2 = fmaf(a[i],a[i],f2);
  }
  f2 = warp_sum(f2);                     // ||GT||_F^2
  float shift = sqrtf(f2) + 1.f;
#pragma unroll
  for(int i=0;i<32;i++) a[i] += (i==lane) ? shift : 0.f;
  float lam = jacobi_vf<MAXSW_SMALL,3>(a, lane, TOLP_SMALL);
  float e = expf(lam - shift);
#pragma unroll
  for(int i=0;i<32;i++) w[i] = a[i]*e;
  mm32_bt(t, w, a, sh, lane);            // expm(GT)
#pragma unroll
  for(int i=0;i<32;i++) q[i] = g_Q[c*1024+i*32+lane];
  mm32(w, q, t, sh, lane);
  mm32(t, w, q, sh, lane);               // BM2
  float lam2 = jacobi_vf<MAXSW_SMALL,3>(t, lane, TOLP_SMALL);   // t -> V of BM2
  float mu   = fmaxf(lam2, EIG_EPS);
#pragma unroll
  for(int i=0;i<32;i++) w[i] = t[i]*rsqrtf(mu);
  mm32_bt(q, w, t, sh, lane);
#pragma unroll
  for(int i=0;i<32;i++) g_AIS[c*1024+i*32+lane] = q[i];
  float me = expf(0.5f*(1.f - pt[0])*logf(mu));
#pragma unroll
  for(int i=0;i<32;i++) w[i] = t[i]*me;
  mm32_bt(q, w, t, sh, lane);
#pragma unroll
  for(int i=0;i<32;i++) g_MSQ[c*1024+i*32+lane] = q[i];
  float psl = 0.f;
  for(int b=lane;b<Bn;b+=32) psl += g_SL2[b*Cn + c];
  float msl2 = warp_sum(psl) * (1.f/Bn);
  float bv = msl2 - f2;
  float sc = std_[c] * rsqrtf(bv + EPS_BN);
  if(lane==0) g_SCALE[c] = sc;
}

// per (b,c): warm-started eigh of Z = AIS X AIS using cached V from phase C:
// W = (AIS V)^T X (AIS V) is nearly diagonal -> few sweeps (NV=2).
// Xn = G G^T, G = MSQ (V Vw) diag(l^{s/2})
__global__ __launch_bounds__(WPB*32,6) void k_phaseF(const float* __restrict__ X,
                                                     float* __restrict__ out){
  extern __shared__ __align__(16) float dsh[];
  int warp = threadIdx.x >> 5, lane = threadIdx.x & 31;
  float* sh = dsh + warp*SH_PER_WARP;
  int task = blockIdx.x*WPB + warp;
  int c = task % Cn;
  float v[32], p[32], t[32], w[32];
  const float* xp = X + (size_t)task*1024;
  const float* vp = g_V + (size_t)task*1024;
#pragma unroll
  for(int i=0;i<32;i++) v[i] = vp[i*32+lane];       // V (cols)
#pragma unroll
  for(int i=0;i<32;i++) t[i] = g_AIS[c*1024+i*32+lane];
  mm32(p, t, v, sh, lane);                 // P = AIS * V
  transp32(t, p, sh, lane);                // Pt
  mm32_bg(t, t, xp, sh, lane);             // Pt * X
  mm32(w, t, p, sh, lane);                 // W = Pt X P  (near diagonal)
  float lam = jacobi_vf<MAXSW_BIG,2>(w, lane, TOLP_BIG);  // w -> Vw
  float sc  = g_SCALE[c];
  float sd  = expf(0.5f*sc * logf(fmaxf(lam, EIG_EPS)));  // lambda^{s/2}
#pragma unroll
  for(int i=0;i<32;i++) t[i] = g_MSQ[c*1024+i*32+lane];
  mm32(v, t, v, sh, lane);                 // H = MSQ * V
  mm32(w, v, w, sh, lane);                 // G0 = H * Vw
#pragma unroll
  for(int i=0;i<32;i++) w[i] *= sd;        // G
  mm32_bt(p, w, w, sh, lane);              // G G^T
  float* op = out + (size_t)task*1024;
#pragma unroll
  for(int i=0;i<32;i++) op[i*32+lane] = p[i];
}

// ================= launcher =================
extern "C" void kernel_launch(void* const* d_in, const int* in_sizes, int n_in,
                              void* d_out, int out_size){
  const float* X     = (const float*)d_in[0];
  const float* std_  = (const float*)d_in[1];
  const float* pt    = (const float*)d_in[4];
  float* out = (float*)d_out;

  cudaFuncSetAttribute(k_phaseC, cudaFuncAttributeMaxDynamicSharedMemorySize, SMEM_BYTES);
  cudaFuncSetAttribute(k_phaseF, cudaFuncAttributeMaxDynamicSharedMemorySize, SMEM_BYTES);

  const int nblk = (Bn*Cn)/WPB;   // 2560 blocks of 4 warps

  k_mean1  <<<dim3(Cn, NSLICE), 256>>>((const float4*)X);
  k_phaseB <<<Cn, 32>>>();
  k_phaseC <<<nblk, WPB*32, SMEM_BYTES>>>(X);
  k_reduce1<<<dim3(Cn, NSLICE), 256>>>();
  k_chan   <<<Cn, 32>>>(std_, pt);
  k_phaseF <<<nblk, WPB*32, SMEM_BYTES>>>(X, out);
}